// round 13
// baseline (speedup 1.0000x reference)
#include <cuda_runtime.h>
#include <math.h>

#define NS    16384
#define NSTEP 16383
#define TPB   512
#define EPT   32
#define ROWL  33                       // 32 + 1 pad word per 32-group
#define SMEM_WORDS (TPB * ROWL)        // 16896 floats = 67584 B
#define SMEM_BYTES (SMEM_WORDS * 4)

__global__ void __launch_bounds__(TPB, 2)
freqgen_kernel(const float* __restrict__ cond,
               const float* __restrict__ wn,
               const float* __restrict__ steps,
               float* __restrict__ out)
{
    extern __shared__ float sm[];      // addr(n) = (n>>5)*33 + (n&31)
    __shared__ float warp_sums[32];

    const int row  = blockIdx.x;
    const int t    = threadIdx.x;
    const int lane = t & 31;
    const int wid  = t >> 5;           // 0..15

    const float* srow = steps + (long long)row * NSTEP;

    // ---- Phase A: coalesced evict-first LDG of scaled steps into smem ----
    // g = t + i*512 -> row = wid + 16*i, offset = lane  (conflict-free STS)
#pragma unroll
    for (int i = 0; i < EPT; ++i) {
        const int g = t + i * TPB;
        float v = (g < NSTEP) ? __fmul_rn(0.01f, __ldcs(srow + g)) : 0.0f;
        sm[(wid + 16 * i) * ROWL + lane] = v;
    }
    __syncthreads();

    // ---- Phase B: in-place local inclusive scan of own row (banks t+k) ----
    float* myrow = sm + t * ROWL;
    float run = 0.0f;
#pragma unroll
    for (int k = 0; k < EPT; ++k) {
        run = __fadd_rn(run, myrow[k]);
        myrow[k] = run;                 // local inclusive cumsum
    }
    const float total = run;

    // block scan of per-thread totals (16 warps)
    float v = total;
#pragma unroll
    for (int o = 1; o < 32; o <<= 1) {
        float u = __shfl_up_sync(0xffffffffu, v, o);
        if (lane >= o) v += u;
    }
    if (lane == 31) warp_sums[wid] = v;
    __syncthreads();
    if (wid == 0) {
        float w = (lane < 16) ? warp_sums[lane] : 0.0f;
#pragma unroll
        for (int o = 1; o < 32; o <<= 1) {
            float u = __shfl_up_sync(0xffffffffu, w, o);
            if (lane >= o) w += u;
        }
        if (lane < 16) warp_sums[lane] = w;
    }
    __syncthreads();
    const float excl = (v - total) + (wid ? warp_sums[wid - 1] : 0.0f);

    // in-row shift: pn[32t+j] = excl + local[j-1], pn[32t] = excl (own row only)
#pragma unroll
    for (int j = EPT - 1; j >= 1; --j)
        myrow[j] = __fadd_rn(excl, myrow[j - 1]);
    myrow[0] = excl;                    // t==0: excl==0 -> pn[0]=0 exactly
    __syncthreads();

    // ---- Phase C: fully-coalesced streaming compute ----
    const float amp = __ldg(cond + row * 3 + 0);
    const float f0  = __ldg(cond + row * 3 + 1);
    const float ph  = __ldg(cond + row * 3 + 2);
    const float cf  = __fmul_rn(6.283185307179586f, f0);  // ref f32 rounding

    const float INV_2PI = 0.15915494309189535f;
    const float PI2_A   = 6.28318548202514648f;   // f32(2*pi)
    const float PI2_Bn  = 1.74845560007e-07f;     // PI2_A - 2*pi (exact tail)
    const float QD      = 0.0078431372549019608f; // f32(2/255)
    const float QH      = 0.0039215686274509804f; // f32(1/255)

    const float4* w4 = (const float4*)(wn  + (long long)row * NS);
    float4*       o4 = (float4*)      (out + (long long)row * NS);

#pragma unroll
    for (int c = 0; c < 8; ++c) {
        const int m = t + c * TPB;                  // float4 group index
        float4 wv = __ldcs(w4 + m);                 // coalesced LDG.128, evict-first
        const int a = (m >> 3) * ROWL + ((m & 7) << 2);
        const float qf = (float)(4 * m);

        float wa[4] = { wv.x, wv.y, wv.z, wv.w };
        float res[4];
#pragma unroll
        for (int j = 0; j < 4; ++j) {
            float pn  = sm[a + j];                  // conflict-free LDS.32
            float nn  = __fadd_rn(qf, (float)j);    // exact (< 2^24)
            float arg = __fadd_rn(__fadd_rn(__fmul_rn(cf, nn), ph), pn);

            // f32 Cody-Waite reduction mod 2*pi (err ~2e-7 rad), MUFU cos
            float q = rintf(__fmul_rn(arg, INV_2PI));
            float r = fmaf(q, -PI2_A, arg);
            r       = fmaf(q,  PI2_Bn, r);
            float xb = __cosf(r);

            float x = __fadd_rn(__fmul_rn(amp, xb), __fmul_rn(0.1f, wa[j]));
            float y = fmaf(QD, floorf(__fmul_rn(x, 127.5f)), QH);
            y = fminf(fmaxf(y, -1.0f), 1.0f);
            res[j] = y;
        }
        __stcs(o4 + m, make_float4(res[0], res[1], res[2], res[3]));  // STG.128 evict-first
    }
}

extern "C" void kernel_launch(void* const* d_in, const int* in_sizes, int n_in,
                              void* d_out, int out_size)
{
    const float* cond  = (const float*)d_in[0];
    const float* wn    = (const float*)d_in[1];
    const float* steps = (const float*)d_in[2];
    float* out = (float*)d_out;

    cudaFuncSetAttribute(freqgen_kernel,
                         cudaFuncAttributeMaxDynamicSharedMemorySize, SMEM_BYTES);

    const int B = in_sizes[0] / 3;   // 4096
    freqgen_kernel<<<B, TPB, SMEM_BYTES>>>(cond, wn, steps, out);
}

// round 14
// speedup vs baseline: 1.2255x; 1.2255x over previous
#include <cuda_runtime.h>
#include <math.h>

#define NS    16384
#define NSTEP 16383
#define TPB   512
#define EPT   32
#define ROWL  33                       // 32 + 1 pad word per 32-group
#define SMEM_WORDS (TPB * ROWL)        // 16896 floats = 67584 B
#define SMEM_BYTES (SMEM_WORDS * 4)

__global__ void __launch_bounds__(TPB, 2)
freqgen_kernel(const float* __restrict__ cond,
               const float* __restrict__ wn,
               const float* __restrict__ steps,
               float* __restrict__ out)
{
    extern __shared__ float sm[];      // addr(n) = (n>>5)*33 + (n&31)
    __shared__ float warp_sums[32];

    const int row  = blockIdx.x;
    const int t    = threadIdx.x;
    const int lane = t & 31;
    const int wid  = t >> 5;           // 0..15

    const float* srow = steps + (long long)row * NSTEP;

    // ---- Phase A: coalesced LDG of scaled steps into padded smem ----
    // g = t + i*512 -> row = wid + 16*i, offset = lane  (conflict-free STS)
#pragma unroll
    for (int i = 0; i < EPT; ++i) {
        const int g = t + i * TPB;
        float v = (g < NSTEP) ? __fmul_rn(0.01f, __ldg(srow + g)) : 0.0f;
        sm[(wid + 16 * i) * ROWL + lane] = v;
    }
    __syncthreads();

    // ---- Phase B: in-place local inclusive scan of own row (banks t+k) ----
    float* myrow = sm + t * ROWL;
    float run = 0.0f;
#pragma unroll
    for (int k = 0; k < EPT; ++k) {
        run = __fadd_rn(run, myrow[k]);
        myrow[k] = run;                 // local inclusive cumsum
    }
    const float total = run;

    // block scan of per-thread totals (16 warps)
    float v = total;
#pragma unroll
    for (int o = 1; o < 32; o <<= 1) {
        float u = __shfl_up_sync(0xffffffffu, v, o);
        if (lane >= o) v += u;
    }
    if (lane == 31) warp_sums[wid] = v;
    __syncthreads();
    if (wid == 0) {
        float w = (lane < 16) ? warp_sums[lane] : 0.0f;
#pragma unroll
        for (int o = 1; o < 32; o <<= 1) {
            float u = __shfl_up_sync(0xffffffffu, w, o);
            if (lane >= o) w += u;
        }
        if (lane < 16) warp_sums[lane] = w;
    }
    __syncthreads();
    const float excl = (v - total) + (wid ? warp_sums[wid - 1] : 0.0f);

    // in-row shift: pn[32t+j] = excl + local[j-1], pn[32t] = excl (own row only)
#pragma unroll
    for (int j = EPT - 1; j >= 1; --j)
        myrow[j] = __fadd_rn(excl, myrow[j - 1]);
    myrow[0] = excl;                    // t==0: excl==0 -> pn[0]=0 exactly
    __syncthreads();

    // ---- Phase C: fully-coalesced streaming compute ----
    const float amp = __ldg(cond + row * 3 + 0);
    const float f0  = __ldg(cond + row * 3 + 1);
    const float ph  = __ldg(cond + row * 3 + 2);
    const float cf  = __fmul_rn(6.283185307179586f, f0);  // ref f32 rounding

    const float INV_2PI = 0.15915494309189535f;
    const float PI2_A   = 6.28318548202514648f;   // f32(2*pi)
    const float PI2_Bn  = 1.74845560007e-07f;     // PI2_A - 2*pi (exact tail)
    const float QD      = 0.0078431372549019608f; // f32(2/255)
    const float QH      = 0.0039215686274509804f; // f32(1/255)

    const float4* w4 = (const float4*)(wn  + (long long)row * NS);
    float4*       o4 = (float4*)      (out + (long long)row * NS);

#pragma unroll
    for (int c = 0; c < 8; ++c) {
        const int m = t + c * TPB;                  // float4 group index
        float4 wv = w4[m];                          // coalesced LDG.128
        const int a = (m >> 3) * ROWL + ((m & 7) << 2);
        const float qf = (float)(4 * m);

        float wa[4] = { wv.x, wv.y, wv.z, wv.w };
        float res[4];
#pragma unroll
        for (int j = 0; j < 4; ++j) {
            float pn  = sm[a + j];                  // conflict-free LDS.32
            float nn  = __fadd_rn(qf, (float)j);    // exact (< 2^24)
            float arg = __fadd_rn(__fadd_rn(__fmul_rn(cf, nn), ph), pn);

            // f32 Cody-Waite reduction mod 2*pi (err ~2e-7 rad), MUFU cos
            float q = rintf(__fmul_rn(arg, INV_2PI));
            float r = fmaf(q, -PI2_A, arg);
            r       = fmaf(q,  PI2_Bn, r);
            float xb = __cosf(r);

            float x = __fadd_rn(__fmul_rn(amp, xb), __fmul_rn(0.1f, wa[j]));
            float y = fmaf(QD, floorf(__fmul_rn(x, 127.5f)), QH);
            y = fminf(fmaxf(y, -1.0f), 1.0f);
            res[j] = y;
        }
        o4[m] = make_float4(res[0], res[1], res[2], res[3]);  // coalesced STG.128
    }
}

extern "C" void kernel_launch(void* const* d_in, const int* in_sizes, int n_in,
                              void* d_out, int out_size)
{
    const float* cond  = (const float*)d_in[0];
    const float* wn    = (const float*)d_in[1];
    const float* steps = (const float*)d_in[2];
    float* out = (float*)d_out;

    cudaFuncSetAttribute(freqgen_kernel,
                         cudaFuncAttributeMaxDynamicSharedMemorySize, SMEM_BYTES);

    const int B = in_sizes[0] / 3;   // 4096
    freqgen_kernel<<<B, TPB, SMEM_BYTES>>>(cond, wn, steps, out);
}